// round 17
// baseline (speedup 1.0000x reference)
#include <cuda_runtime.h>
#include <cuda_fp16.h>
#include <mma.h>
#include <cstdint>

using namespace nvcuda;

// Fixed shapes
#define B_      2
#define L_      512
#define D_      256
#define TILE    64
#define THREADS 512
#define SST     264                      // fp16 row stride: 256 + 8 pad (528B)
#define TEL     (TILE * SST)
#define SMEM_BYTES (2 * TEL * 2)         // 67584 B

// out[b,i,j] = sum_d x[b,i,d]*w1[d]*x[b,j,d] + bias   (symmetric)
// (lin_i - lin_j cancels under (P+P^T)/2; w2 = W[D:,0] dead.)
// fp16 single product, f32 accumulate: rel err ~2.9e-4 < 1e-3 (measured).
//
// 4-chunk producer/consumer pipeline:
//   phase A : all 512 threads convert K-chunk 0
//   then    : warps 0-11 produce chunks 1..3 (bar.arrive),
//             warps 12-15 (high arbiter priority) consume with MMA (bar.sync)

__device__ __forceinline__ uint32_t h2(float a, float b) {
    __half2 h = __floats2half2_rn(a, b);
    return *reinterpret_cast<uint32_t*>(&h);
}
__device__ __forceinline__ uint4 pack8(float4 f0, float4 f1) {
    uint4 v;
    v.x = h2(f0.x, f0.y);
    v.y = h2(f0.z, f0.w);
    v.z = h2(f1.x, f1.y);
    v.w = h2(f1.z, f1.w);
    return v;
}
__device__ __forceinline__ float4 mul4(float4 a, float4 w) {
    a.x *= w.x; a.y *= w.y; a.z *= w.z; a.w *= w.w;
    return a;
}

__global__ __launch_bounds__(THREADS, 1)
void fused_pairwise_kernel(const float* __restrict__ x,
                           const float* __restrict__ W,
                           const float* __restrict__ bias_p,
                           float* __restrict__ out) {
    extern __shared__ __align__(16) __half smem[];
    __half* sB = smem;            // fp16(x), j-strip rows
    __half* sA = smem + TEL;      // fp16(x*w1), i-strip rows

    const int bz  = blockIdx.z;
    const int ti  = blockIdx.y;
    const int tj  = blockIdx.x;
    const int tid = threadIdx.x;
    const int warp = tid >> 5;

    const float bias = __ldg(bias_p);

    const float4* A4 = (const float4*)(x + (size_t)(bz * L_ + ti * TILE) * D_);
    const float4* B4 = (const float4*)(x + (size_t)(bz * L_ + tj * TILE) * D_);
    const float4* W4 = (const float4*)W;  // w1 = W[:256] -> f4 cols 0..63

    // ============ phase A: chunk 0 (f4 cols 0..15), all 512 threads ========
    // unit = (m, row, pc): m in {B,A}, row 0..63, pc 0..7 (pair of f4 cols)
    #pragma unroll
    for (int t = 0; t < 2; t++) {
        const int u   = tid + t * 512;     // t==0 -> B units, t==1 -> A units
        const int m   = u >> 9;
        const int rem = u & 511;
        const int row = rem >> 3;
        const int cf4 = (rem & 7) * 2;     // f4 cols 0..14
        const float4* S = m ? A4 : B4;
        __half* dst = m ? sA : sB;
        float4 f0 = S[row * 64 + cf4];
        float4 f1 = S[row * 64 + cf4 + 1];
        if (m) {
            f0 = mul4(f0, __ldg(&W4[cf4]));
            f1 = mul4(f1, __ldg(&W4[cf4 + 1]));
        }
        *(uint4*)&dst[row * SST + cf4 * 4] = pack8(f0, f1);
    }
    __syncthreads();

    // ============ producers: warps 0-11 stream chunks 1..3 =================
    if (warp < 12) {
        #pragma unroll
        for (int c = 1; c < 4; c++) {
            for (int u = tid; u < 1024; u += 384) {
                const int m   = u >> 9;
                const int rem = u & 511;
                const int row = rem >> 3;
                const int cf4 = c * 16 + (rem & 7) * 2;
                const float4* S = m ? A4 : B4;
                __half* dst = m ? sA : sB;
                float4 f0 = S[row * 64 + cf4];
                float4 f1 = S[row * 64 + cf4 + 1];
                if (m) {
                    f0 = mul4(f0, __ldg(&W4[cf4]));
                    f1 = mul4(f1, __ldg(&W4[cf4 + 1]));
                }
                *(uint4*)&dst[row * SST + cf4 * 4] = pack8(f0, f1);
            }
            asm volatile("bar.arrive %0, %1;" :: "r"(c), "r"(512) : "memory");
        }
        return;   // producers done; SM belongs to MMA warps for the tail
    }

    // ============ consumers: warps 12-15, one per SMSP (top priority) ======
    const int mw = warp - 12;
    const int wr = (mw >> 1) & 1;
    const int wc = mw & 1;

    wmma::fragment<wmma::accumulator, 16, 16, 16, float> acc[2][2];
    #pragma unroll
    for (int r = 0; r < 2; r++)
        #pragma unroll
        for (int c = 0; c < 2; c++)
            wmma::fill_fragment(acc[r][c], bias);   // bias folded into init

    const __half* Ab = sA + (wr * 32) * SST;
    const __half* Bb = sB + (wc * 32) * SST;

    #pragma unroll
    for (int c = 0; c < 4; c++) {
        if (c > 0)
            asm volatile("bar.sync %0, %1;" :: "r"(c), "r"(512) : "memory");
        #pragma unroll
        for (int kk = c * 64; kk < c * 64 + 64; kk += 16) {
            wmma::fragment<wmma::matrix_a, 16, 16, 16, __half, wmma::row_major> af[2];
            wmma::fragment<wmma::matrix_b, 16, 16, 16, __half, wmma::col_major> bf[2];
            #pragma unroll
            for (int r = 0; r < 2; r++)
                wmma::load_matrix_sync(af[r], Ab + r * 16 * SST + kk, SST);
            #pragma unroll
            for (int cc = 0; cc < 2; cc++)
                wmma::load_matrix_sync(bf[cc], Bb + cc * 16 * SST + kk, SST);
            #pragma unroll
            for (int r = 0; r < 2; r++)
                #pragma unroll
                for (int cc = 0; cc < 2; cc++)
                    wmma::mma_sync(acc[r][cc], af[r], bf[cc], acc[r][cc]);
        }
    }

    // ---- epilogue: store (bias already in acc) ----
    #pragma unroll
    for (int r = 0; r < 2; r++) {
        #pragma unroll
        for (int c = 0; c < 2; c++) {
            int gi = ti * TILE + wr * 32 + r * 16;
            int gj = tj * TILE + wc * 32 + c * 16;
            float* dst = out + (size_t)bz * L_ * L_ + (size_t)gi * L_ + gj;
            wmma::store_matrix_sync(dst, acc[r][c], L_, wmma::mem_row_major);
        }
    }
}

// ---------------------------------------------------------------------------
// d_in[0] = inputs f32 (2,512,256), d_in[1] = W f32 (512,1), d_in[2] = b f32 (1,)
// d_out   = f32 (2,512,512,1)
// ---------------------------------------------------------------------------
extern "C" void kernel_launch(void* const* d_in, const int* in_sizes, int n_in,
                              void* d_out, int out_size) {
    const float* x    = (const float*)d_in[0];
    const float* W    = (const float*)d_in[1];
    const float* bptr = (const float*)d_in[2];
    float* out = (float*)d_out;

    static bool attr_set = false;
    if (!attr_set) {
        cudaFuncSetAttribute(fused_pairwise_kernel,
                             cudaFuncAttributeMaxDynamicSharedMemorySize, SMEM_BYTES);
        attr_set = true;
    }

    dim3 grid(L_ / TILE, L_ / TILE, B_);   // (8, 8, 2) = 128 CTAs, single wave
    fused_pairwise_kernel<<<grid, THREADS, SMEM_BYTES>>>(x, W, bptr, out);
}